// round 16
// baseline (speedup 1.0000x reference)
#include <cuda_runtime.h>
#include <cstdint>

// TransOp expm: out[b, s*8..] = expm(A_{b,s}) @ x[b, s*8..]
// A_{b,s} = sum_m c[b,m] * psi[m,s,:,:]  (8x8). Thread = problem.
//
// smem: psi slice pre-paired row-wise (NOT duplicated):
//   ps2[m][i*8+k] = { psi[m,s,2i,k], psi[m,s,2i+1,k] }   (4 KB)
// A-build: A2[j] (row-pair packed) accumulated with FFMA2 from warp-uniform
// LDS.128 reads (broadcast) and a per-m dup2(c[m]) multiplier.
//
// Taylor action, warp-uniform (order m, reps r) from warp-max ||A||_inf:
//   <=2.6: m=7  <=3.6: m=9  <=4.8: m=11  <=6.0: m=13  <=7.2: m=16
//   else: r = ceil(wmax/3.2), m=13, A scaled by 1/r.
// Horner: v = b; for j=m..1: v = b + (A v)/j.   All heavy FP is FFMA2.
// Each 8-term dot is split into two independent 4-deep chains (k=0..3 and
// k=4..7) combined with one add2 -> ILP 8, step critical path ~32 cyc.

typedef unsigned long long ull;

#define BDIM 128

__constant__ float2 INV2[32] = {
    {0.0f,0.0f},       {1.0f,1.0f},       {1.0f/2,1.0f/2},   {1.0f/3,1.0f/3},
    {1.0f/4,1.0f/4},   {1.0f/5,1.0f/5},   {1.0f/6,1.0f/6},   {1.0f/7,1.0f/7},
    {1.0f/8,1.0f/8},   {1.0f/9,1.0f/9},   {1.0f/10,1.0f/10}, {1.0f/11,1.0f/11},
    {1.0f/12,1.0f/12}, {1.0f/13,1.0f/13}, {1.0f/14,1.0f/14}, {1.0f/15,1.0f/15},
    {1.0f/16,1.0f/16}, {1.0f/17,1.0f/17}, {1.0f/18,1.0f/18}, {1.0f/19,1.0f/19},
    {1.0f/20,1.0f/20}, {1.0f/21,1.0f/21}, {1.0f/22,1.0f/22}, {1.0f/23,1.0f/23},
    {1.0f/24,1.0f/24}, {1.0f/25,1.0f/25}, {1.0f/26,1.0f/26}, {1.0f/27,1.0f/27},
    {1.0f/28,1.0f/28}, {1.0f/29,1.0f/29}, {1.0f/30,1.0f/30}, {1.0f/31,1.0f/31}
};

__device__ __forceinline__ ull dup2(float v) {
    ull r; asm("mov.b64 %0, {%1,%1};" : "=l"(r) : "f"(v)); return r;
}
__device__ __forceinline__ ull pack2(float lo, float hi) {
    ull r; asm("mov.b64 %0, {%1,%2};" : "=l"(r) : "f"(lo), "f"(hi)); return r;
}
__device__ __forceinline__ void unpack2(ull v, float& lo, float& hi) {
    asm("mov.b64 {%0,%1}, %2;" : "=f"(lo), "=f"(hi) : "l"(v));
}
__device__ __forceinline__ ull fma2(ull a, ull b, ull c) {
    ull d; asm("fma.rn.f32x2 %0, %1, %2, %3;" : "=l"(d) : "l"(a), "l"(b), "l"(c)); return d;
}
__device__ __forceinline__ ull mul2(ull a, ull b) {
    ull d; asm("mul.rn.f32x2 %0, %1, %2;" : "=l"(d) : "l"(a), "l"(b)); return d;
}
__device__ __forceinline__ ull add2(ull a, ull b) {
    ull d; asm("add.rn.f32x2 %0, %1, %2;" : "=l"(d) : "l"(a), "l"(b)); return d;
}

__global__ __launch_bounds__(BDIM, 4) void transop_expm_kernel(
    const float* __restrict__ x,
    const float* __restrict__ c,
    const float* __restrict__ psi,
    float* __restrict__ out)
{
    // Row-paired psi slice for this CTA's s (4 KB, not duplicated).
    __shared__ ull ps2[16][32];

    const int s = blockIdx.x & 63;
    const int t = threadIdx.x;
    const int b = (blockIdx.x >> 6) * BDIM + t;   // thread = problem

    // Stage: 128 threads; thread covers (m = t>>3, i2 = (t&7)>>1, k0 = (t&1)*4).
    {
        const int m  = t >> 3;
        const int q  = t & 7;
        const int i2 = q >> 1;
        const int k0 = (q & 1) << 2;
        const float* src = psi + ((m * 64 + s) << 6) + i2 * 16 + k0;
        const float4 r0 = *reinterpret_cast<const float4*>(src);       // row 2i2
        const float4 r1 = *reinterpret_cast<const float4*>(src + 8);   // row 2i2+1
        ps2[m][i2 * 8 + k0 + 0] = pack2(r0.x, r1.x);
        ps2[m][i2 * 8 + k0 + 1] = pack2(r0.y, r1.y);
        ps2[m][i2 * 8 + k0 + 2] = pack2(r0.z, r1.z);
        ps2[m][i2 * 8 + k0 + 3] = pack2(r0.w, r1.w);
    }
    __syncthreads();

    // A-build: A2[j] = {A[2i][k], A[2i+1][k]}, j = i*8+k. LDS.128 per access,
    // warp-uniform addresses -> broadcast wavefronts.
    const ulonglong2* pp = reinterpret_cast<const ulonglong2*>(&ps2[0][0]);
    const float4* cr = reinterpret_cast<const float4*>(c + (size_t)b * 16);

    ull A2[32];
#pragma unroll
    for (int mc = 0; mc < 4; ++mc) {           // c in 4-wide chunks (reg cap)
        const float4 cv = cr[mc];
        const float cf[4] = {cv.x, cv.y, cv.z, cv.w};
#pragma unroll
        for (int mm = 0; mm < 4; ++mm) {
            const int m = mc * 4 + mm;
            const ull cd = dup2(cf[mm]);
#pragma unroll
            for (int u = 0; u < 16; ++u) {
                const ulonglong2 z = pp[m * 16 + u];
                if (m == 0) {
                    A2[2 * u + 0] = mul2(cd, z.x);
                    A2[2 * u + 1] = mul2(cd, z.y);
                } else {
                    A2[2 * u + 0] = fma2(cd, z.x, A2[2 * u + 0]);
                    A2[2 * u + 1] = fma2(cd, z.y, A2[2 * u + 1]);
                }
            }
        }
    }

    // Infinity norm (packed abs row sums) -> warp-uniform tier.
    float ninf = 0.0f;
    {
        const ull mask = 0x7FFFFFFF7FFFFFFFULL;
#pragma unroll
        for (int i = 0; i < 4; ++i) {
            ull acc = A2[i * 8] & mask;
#pragma unroll
            for (int k = 1; k < 8; ++k) acc = add2(acc, A2[i * 8 + k] & mask);
            float a0, a1; unpack2(acc, a0, a1);
            ninf = fmaxf(ninf, fmaxf(a0, a1));
        }
    }
    const float wmax = __uint_as_float(
        __reduce_max_sync(0xffffffffu, __float_as_uint(ninf)));

    int m_ord, reps;
    if (wmax <= 2.6f)       { m_ord = 7;  reps = 1; }
    else if (wmax <= 3.6f)  { m_ord = 9;  reps = 1; }
    else if (wmax <= 4.8f)  { m_ord = 11; reps = 1; }
    else if (wmax <= 6.0f)  { m_ord = 13; reps = 1; }
    else if (wmax <= 7.2f)  { m_ord = 16; reps = 1; }
    else {
        reps = (int)ceilf(wmax * (1.0f / 3.2f));
        if (reps > 31) reps = 31;
        m_ord = 13;
    }

    if (reps > 1) {
        const ull s2 = *reinterpret_cast<const ull*>(&INV2[reps]);
#pragma unroll
        for (int i = 0; i < 32; ++i) A2[i] = mul2(A2[i], s2);
    }

    // x block: natural element pairs match the row-pair packing.
    ull v2[4];
    {
        const float4 xa = *reinterpret_cast<const float4*>(x + (size_t)b * 512 + s * 8);
        const float4 xb = *reinterpret_cast<const float4*>(x + (size_t)b * 512 + s * 8 + 4);
        v2[0] = pack2(xa.x, xa.y);
        v2[1] = pack2(xa.z, xa.w);
        v2[2] = pack2(xb.x, xb.y);
        v2[3] = pack2(xb.z, xb.w);
    }

    // reps repetitions of order-m Horner Taylor action.
    // Two independent 4-deep chains per row-pair (ILP 8).
    for (int rr = 0; rr < reps; ++rr) {
        const ull b2_0 = v2[0], b2_1 = v2[1], b2_2 = v2[2], b2_3 = v2[3];
        for (int j = m_ord; j > 0; --j) {
            float vf[8];
            unpack2(v2[0], vf[0], vf[1]);
            unpack2(v2[1], vf[2], vf[3]);
            unpack2(v2[2], vf[4], vf[5]);
            unpack2(v2[3], vf[6], vf[7]);
            ull dm[8];
#pragma unroll
            for (int k = 0; k < 8; ++k) dm[k] = dup2(vf[k]);

            // Low chains: k = 0..3
            ull u0 = mul2(A2[0],  dm[0]);
            ull u1 = mul2(A2[8],  dm[0]);
            ull u2 = mul2(A2[16], dm[0]);
            ull u3 = mul2(A2[24], dm[0]);
            // High chains: k = 4..7
            ull h0 = mul2(A2[4],  dm[4]);
            ull h1 = mul2(A2[12], dm[4]);
            ull h2 = mul2(A2[20], dm[4]);
            ull h3 = mul2(A2[28], dm[4]);
#pragma unroll
            for (int k = 1; k < 4; ++k) {
                u0 = fma2(A2[0  + k], dm[k], u0);
                u1 = fma2(A2[8  + k], dm[k], u1);
                u2 = fma2(A2[16 + k], dm[k], u2);
                u3 = fma2(A2[24 + k], dm[k], u3);
                h0 = fma2(A2[4  + k], dm[4 + k], h0);
                h1 = fma2(A2[12 + k], dm[4 + k], h1);
                h2 = fma2(A2[20 + k], dm[4 + k], h2);
                h3 = fma2(A2[28 + k], dm[4 + k], h3);
            }

            const ull sj = *reinterpret_cast<const ull*>(&INV2[j]);
            v2[0] = fma2(add2(u0, h0), sj, b2_0);
            v2[1] = fma2(add2(u1, h1), sj, b2_1);
            v2[2] = fma2(add2(u2, h2), sj, b2_2);
            v2[3] = fma2(add2(u3, h3), sj, b2_3);
        }
    }

    // Store 8 outputs (two STG.128).
    {
        float y0, y1, y2, y3, y4, y5, y6, y7;
        unpack2(v2[0], y0, y1);
        unpack2(v2[1], y2, y3);
        unpack2(v2[2], y4, y5);
        unpack2(v2[3], y6, y7);
        float4* ob = reinterpret_cast<float4*>(out + (size_t)b * 512 + s * 8);
        ob[0] = make_float4(y0, y1, y2, y3);
        ob[1] = make_float4(y4, y5, y6, y7);
    }
}

extern "C" void kernel_launch(void* const* d_in, const int* in_sizes, int n_in,
                              void* d_out, int out_size)
{
    const float* x   = (const float*)d_in[0];   // (B, 512)
    const float* c   = (const float*)d_in[1];   // (B, 16)
    const float* psi = (const float*)d_in[2];   // (16, 64, 8, 8)
    float* out = (float*)d_out;                 // (B, 512)

    const int B = in_sizes[0] / 512;            // 8192
    // Each CTA: one s, 128 problems (thread = problem).
    const dim3 grid((B / BDIM) * 64);           // 4096 CTAs
    transop_expm_kernel<<<grid, BDIM>>>(x, c, psi, out);
}

// round 17
// speedup vs baseline: 1.0078x; 1.0078x over previous
#include <cuda_runtime.h>
#include <cstdint>

// TransOp expm: out[b, s*8..] = expm(A_{b,s}) @ x[b, s*8..]
// A_{b,s} = sum_m c[b,m] * psi[m,s,:,:]  (8x8). Thread = problem.
//
// smem: psi slice pre-paired row-wise (NOT duplicated):
//   ps2[m][i*8+k] = { psi[m,s,2i,k], psi[m,s,2i+1,k] }   (4 KB)
// A-build: A2[j] (row-pair packed) accumulated with FFMA2 from warp-uniform
// LDS.128 reads (broadcast) and a per-m dup2(c[m]) multiplier.
//
// Taylor action, warp-uniform (order m, reps r) from warp-max ||A||_inf:
//   <=2.6: m=7  <=3.6: m=9  <=4.8: m=11  <=6.0: m=13  <=7.2: m=16
//   else: r = ceil(wmax/3.2), m=13, A scaled by 1/r.
// Horner: v = b; for j=m..1: v = b + (A v)/j.   All heavy FP is FFMA2.
//
// Register diet: k-major matvec (one dup2 at a time feeding 4 row-chains,
// ILP 4) keeps the live set ~100 regs -> launch_bounds(128,5) = 20 warps/SM.

typedef unsigned long long ull;

#define BDIM 128

__constant__ float2 INV2[32] = {
    {0.0f,0.0f},       {1.0f,1.0f},       {1.0f/2,1.0f/2},   {1.0f/3,1.0f/3},
    {1.0f/4,1.0f/4},   {1.0f/5,1.0f/5},   {1.0f/6,1.0f/6},   {1.0f/7,1.0f/7},
    {1.0f/8,1.0f/8},   {1.0f/9,1.0f/9},   {1.0f/10,1.0f/10}, {1.0f/11,1.0f/11},
    {1.0f/12,1.0f/12}, {1.0f/13,1.0f/13}, {1.0f/14,1.0f/14}, {1.0f/15,1.0f/15},
    {1.0f/16,1.0f/16}, {1.0f/17,1.0f/17}, {1.0f/18,1.0f/18}, {1.0f/19,1.0f/19},
    {1.0f/20,1.0f/20}, {1.0f/21,1.0f/21}, {1.0f/22,1.0f/22}, {1.0f/23,1.0f/23},
    {1.0f/24,1.0f/24}, {1.0f/25,1.0f/25}, {1.0f/26,1.0f/26}, {1.0f/27,1.0f/27},
    {1.0f/28,1.0f/28}, {1.0f/29,1.0f/29}, {1.0f/30,1.0f/30}, {1.0f/31,1.0f/31}
};

__device__ __forceinline__ ull dup2(float v) {
    ull r; asm("mov.b64 %0, {%1,%1};" : "=l"(r) : "f"(v)); return r;
}
__device__ __forceinline__ ull pack2(float lo, float hi) {
    ull r; asm("mov.b64 %0, {%1,%2};" : "=l"(r) : "f"(lo), "f"(hi)); return r;
}
__device__ __forceinline__ void unpack2(ull v, float& lo, float& hi) {
    asm("mov.b64 {%0,%1}, %2;" : "=f"(lo), "=f"(hi) : "l"(v));
}
__device__ __forceinline__ ull fma2(ull a, ull b, ull c) {
    ull d; asm("fma.rn.f32x2 %0, %1, %2, %3;" : "=l"(d) : "l"(a), "l"(b), "l"(c)); return d;
}
__device__ __forceinline__ ull mul2(ull a, ull b) {
    ull d; asm("mul.rn.f32x2 %0, %1, %2;" : "=l"(d) : "l"(a), "l"(b)); return d;
}
__device__ __forceinline__ ull add2(ull a, ull b) {
    ull d; asm("add.rn.f32x2 %0, %1, %2;" : "=l"(d) : "l"(a), "l"(b)); return d;
}

__global__ __launch_bounds__(BDIM, 5) void transop_expm_kernel(
    const float* __restrict__ x,
    const float* __restrict__ c,
    const float* __restrict__ psi,
    float* __restrict__ out)
{
    // Row-paired psi slice for this CTA's s (4 KB, not duplicated).
    __shared__ ull ps2[16][32];

    const int s = blockIdx.x & 63;
    const int t = threadIdx.x;
    const int b = (blockIdx.x >> 6) * BDIM + t;   // thread = problem

    // Stage: 128 threads; thread covers (m = t>>3, i2 = (t&7)>>1, k0 = (t&1)*4).
    {
        const int m  = t >> 3;
        const int q  = t & 7;
        const int i2 = q >> 1;
        const int k0 = (q & 1) << 2;
        const float* src = psi + ((m * 64 + s) << 6) + i2 * 16 + k0;
        const float4 r0 = *reinterpret_cast<const float4*>(src);       // row 2i2
        const float4 r1 = *reinterpret_cast<const float4*>(src + 8);   // row 2i2+1
        ps2[m][i2 * 8 + k0 + 0] = pack2(r0.x, r1.x);
        ps2[m][i2 * 8 + k0 + 1] = pack2(r0.y, r1.y);
        ps2[m][i2 * 8 + k0 + 2] = pack2(r0.z, r1.z);
        ps2[m][i2 * 8 + k0 + 3] = pack2(r0.w, r1.w);
    }
    __syncthreads();

    // A-build: A2[j] = {A[2i][k], A[2i+1][k]}, j = i*8+k. LDS.128 per access,
    // warp-uniform addresses -> broadcast wavefronts.
    const ulonglong2* pp = reinterpret_cast<const ulonglong2*>(&ps2[0][0]);
    const float4* cr = reinterpret_cast<const float4*>(c + (size_t)b * 16);

    ull A2[32];
#pragma unroll
    for (int mc = 0; mc < 4; ++mc) {           // c in 4-wide chunks (reg cap)
        const float4 cv = cr[mc];
        const float cf[4] = {cv.x, cv.y, cv.z, cv.w};
#pragma unroll
        for (int mm = 0; mm < 4; ++mm) {
            const int m = mc * 4 + mm;
            const ull cd = dup2(cf[mm]);
#pragma unroll
            for (int u = 0; u < 16; ++u) {
                const ulonglong2 z = pp[m * 16 + u];
                if (m == 0) {
                    A2[2 * u + 0] = mul2(cd, z.x);
                    A2[2 * u + 1] = mul2(cd, z.y);
                } else {
                    A2[2 * u + 0] = fma2(cd, z.x, A2[2 * u + 0]);
                    A2[2 * u + 1] = fma2(cd, z.y, A2[2 * u + 1]);
                }
            }
        }
    }

    // Infinity norm (packed abs row sums) -> warp-uniform tier.
    float ninf = 0.0f;
    {
        const ull mask = 0x7FFFFFFF7FFFFFFFULL;
#pragma unroll
        for (int i = 0; i < 4; ++i) {
            ull acc = A2[i * 8] & mask;
#pragma unroll
            for (int k = 1; k < 8; ++k) acc = add2(acc, A2[i * 8 + k] & mask);
            float a0, a1; unpack2(acc, a0, a1);
            ninf = fmaxf(ninf, fmaxf(a0, a1));
        }
    }
    const float wmax = __uint_as_float(
        __reduce_max_sync(0xffffffffu, __float_as_uint(ninf)));

    int m_ord, reps;
    if (wmax <= 2.6f)       { m_ord = 7;  reps = 1; }
    else if (wmax <= 3.6f)  { m_ord = 9;  reps = 1; }
    else if (wmax <= 4.8f)  { m_ord = 11; reps = 1; }
    else if (wmax <= 6.0f)  { m_ord = 13; reps = 1; }
    else if (wmax <= 7.2f)  { m_ord = 16; reps = 1; }
    else {
        reps = (int)ceilf(wmax * (1.0f / 3.2f));
        if (reps > 31) reps = 31;
        m_ord = 13;
    }

    if (reps > 1) {
        const ull s2 = *reinterpret_cast<const ull*>(&INV2[reps]);
#pragma unroll
        for (int i = 0; i < 32; ++i) A2[i] = mul2(A2[i], s2);
    }

    // x block: natural element pairs match the row-pair packing.
    ull v2[4];
    {
        const float4 xa = *reinterpret_cast<const float4*>(x + (size_t)b * 512 + s * 8);
        const float4 xb = *reinterpret_cast<const float4*>(x + (size_t)b * 512 + s * 8 + 4);
        v2[0] = pack2(xa.x, xa.y);
        v2[1] = pack2(xa.z, xa.w);
        v2[2] = pack2(xb.x, xb.y);
        v2[3] = pack2(xb.z, xb.w);
    }

    // reps repetitions of order-m Horner Taylor action.
    // k-major: one dup2 feeds 4 row-chains (ILP 4), minimal live registers.
    for (int rr = 0; rr < reps; ++rr) {
        const ull b2_0 = v2[0], b2_1 = v2[1], b2_2 = v2[2], b2_3 = v2[3];
        for (int j = m_ord; j > 0; --j) {
            float vf[8];
            unpack2(v2[0], vf[0], vf[1]);
            unpack2(v2[1], vf[2], vf[3]);
            unpack2(v2[2], vf[4], vf[5]);
            unpack2(v2[3], vf[6], vf[7]);

            ull dm = dup2(vf[0]);
            ull w0 = mul2(A2[0],  dm);
            ull w1 = mul2(A2[8],  dm);
            ull w2 = mul2(A2[16], dm);
            ull w3 = mul2(A2[24], dm);
#pragma unroll
            for (int k = 1; k < 8; ++k) {
                dm = dup2(vf[k]);
                w0 = fma2(A2[0  + k], dm, w0);
                w1 = fma2(A2[8  + k], dm, w1);
                w2 = fma2(A2[16 + k], dm, w2);
                w3 = fma2(A2[24 + k], dm, w3);
            }

            const ull sj = *reinterpret_cast<const ull*>(&INV2[j]);
            v2[0] = fma2(w0, sj, b2_0);
            v2[1] = fma2(w1, sj, b2_1);
            v2[2] = fma2(w2, sj, b2_2);
            v2[3] = fma2(w3, sj, b2_3);
        }
    }

    // Store 8 outputs (two STG.128).
    {
        float y0, y1, y2, y3, y4, y5, y6, y7;
        unpack2(v2[0], y0, y1);
        unpack2(v2[1], y2, y3);
        unpack2(v2[2], y4, y5);
        unpack2(v2[3], y6, y7);
        float4* ob = reinterpret_cast<float4*>(out + (size_t)b * 512 + s * 8);
        ob[0] = make_float4(y0, y1, y2, y3);
        ob[1] = make_float4(y4, y5, y6, y7);
    }
}

extern "C" void kernel_launch(void* const* d_in, const int* in_sizes, int n_in,
                              void* d_out, int out_size)
{
    const float* x   = (const float*)d_in[0];   // (B, 512)
    const float* c   = (const float*)d_in[1];   // (B, 16)
    const float* psi = (const float*)d_in[2];   // (16, 64, 8, 8)
    float* out = (float*)d_out;                 // (B, 512)

    const int B = in_sizes[0] / 512;            // 8192
    // Each CTA: one s, 128 problems (thread = problem).
    const dim3 grid((B / BDIM) * 64);           // 4096 CTAs
    transop_expm_kernel<<<grid, BDIM>>>(x, c, psi, out);
}